// round 15
// baseline (speedup 1.0000x reference)
#include <cuda_runtime.h>
#include <cuda_fp16.h>
#include <cstdint>
#include <math.h>

#define B_ 8
#define N_ 2048
#define M_ 2048
#define D_ 256
#define KS_ 512                  // 2 fp16 limbs x 256
#define KC 64                    // fp16 k per chunk (128-byte rows, SW128)
#define NTILES (M_ / 128)        // 16
#define TSC (NTILES * 4)         // 64 super-chunk steps (tile, kc)
#define THREADS 512

#define A_OFF 0
#define B_OFF 131072             // A: 8 chunks * 16KB = 128KB
#define SMEM_BYTES (131072 + 3 * 32768)   // + 3-deep 32KB super-chunk ring

#define CROSS_SCALE 2.44140625e-4f   // 2^-12

// Split-fp16 operands (pre-normalized rows): [x0 (256) | x1*2^12 (256)]
__device__ __half gA[(size_t)B_ * N_ * KS_];
__device__ __half gBt[(size_t)B_ * M_ * KS_];

#define SWZ(x) ((x) ^ (((x) >> 3) & 0x70))

__device__ __forceinline__ uint32_t smem_u32(const void* p) {
    uint32_t a;
    asm("{ .reg .u64 t; cvta.to.shared.u64 t, %1; cvt.u32.u64 %0, t; }"
        : "=r"(a) : "l"(p));
    return a;
}
__device__ __forceinline__ void cp_async16(uint32_t dst, const void* src) {
    asm volatile("cp.async.cg.shared.global [%0], [%1], 16;"
                 :: "r"(dst), "l"(src) : "memory");
}
__device__ __forceinline__ void cp_commit() {
    asm volatile("cp.async.commit_group;" ::: "memory");
}
template <int N>
__device__ __forceinline__ void cp_wait() {
    asm volatile("cp.async.wait_group %0;" :: "n"(N) : "memory");
}
// Non-trans ldmatrix for BOTH operands (NT pair for mma .row.col), verified.
__device__ __forceinline__ void ldm_x4(uint32_t* r, uint32_t addr) {
    asm volatile("ldmatrix.sync.aligned.m8n8.x4.shared.b16 {%0,%1,%2,%3}, [%4];"
                 : "=r"(r[0]), "=r"(r[1]), "=r"(r[2]), "=r"(r[3]) : "r"(addr));
}
__device__ __forceinline__ void mma16816(float* d, const uint32_t* a,
                                         const uint32_t* b) {
    asm volatile(
        "mma.sync.aligned.m16n8k16.row.col.f32.f16.f16.f32 "
        "{%0,%1,%2,%3}, {%4,%5,%6,%7}, {%8,%9}, {%0,%1,%2,%3};"
        : "+f"(d[0]), "+f"(d[1]), "+f"(d[2]), "+f"(d[3])
        : "r"(a[0]), "r"(a[1]), "r"(a[2]), "r"(a[3]), "r"(b[0]), "r"(b[1]));
}

// ---------------------------------------------------------------------------
// Kernel 1: normalize rows, split fp32 -> 2 fp16 limbs (limb1 scaled 2^12).
// ---------------------------------------------------------------------------
__global__ void prep_kernel(const float* __restrict__ src,
                            const float* __restrict__ dst) {
    int gw = (blockIdx.x * blockDim.x + threadIdx.x) >> 5;
    int lane = threadIdx.x & 31;
    if (gw >= B_ * (N_ + M_)) return;
    bool is_src = gw < B_ * N_;
    int row = is_src ? gw : gw - B_ * N_;
    const float* p = (is_src ? src : dst) + (size_t)row * D_;
    __half* o = (is_src ? gA : gBt) + (size_t)row * KS_;

    float4 v0 = ((const float4*)p)[lane * 2];
    float4 v1 = ((const float4*)p)[lane * 2 + 1];
    float x[8] = {v0.x, v0.y, v0.z, v0.w, v1.x, v1.y, v1.z, v1.w};
    float s = 0.f;
    #pragma unroll
    for (int i = 0; i < 8; i++) s = fmaf(x[i], x[i], s);
    #pragma unroll
    for (int o2 = 16; o2 > 0; o2 >>= 1) s += __shfl_xor_sync(0xffffffffu, s, o2);
    float scale = 1.0f / sqrtf(s);

    __align__(16) __half t0[8], t1[8];
    #pragma unroll
    for (int i = 0; i < 8; i++) {
        float v = x[i] * scale;
        __half h0 = __float2half_rn(v);
        float r = v - __half2float(h0);
        t0[i] = h0;
        t1[i] = __float2half_rn(r * 4096.0f);   // 2^12 pre-scale
    }
    ((uint4*)(o))[lane]       = *(uint4*)t0;
    ((uint4*)(o + 256))[lane] = *(uint4*)t1;
}

// Load one 32KB B super-chunk (y0[kc] | y1[kc]) into ring buffer `buf`.
__device__ __forceinline__ void load_super(uint32_t sb, const __half* gBb,
                                           int t, int kc, int buf, int tid) {
    const uint32_t dstb = sb + B_OFF + buf * 32768;
    #pragma unroll
    for (int i = 0; i < 4; ++i) {
        int idx = tid + i * THREADS;
        int half = idx >> 10;            // 0: y0 limb, 1: y1 limb
        int rem = idx & 1023;
        int r = rem >> 3, q = rem & 7;
        const __half* src = gBb + (size_t)(t * 128 + r) * KS_ + (half * 4 + kc) * KC;
        cp_async16(dstb + half * 16384 + SWZ(r * 128 + q * 16),
                   (const char*)src + q * 16);
    }
}

// ---------------------------------------------------------------------------
// Kernel 2: fp16 mma.sync GEMM, 16 warps (4x4 warp grid, 32x32 warp tile),
// uniform super-chunks, 3-deep cp.async ring, one barrier per step,
// fused argmax + gather.
// ---------------------------------------------------------------------------
__global__ __launch_bounds__(THREADS, 1)
void match_mma_kernel(const float* __restrict__ pts, float* __restrict__ out) {
    extern __shared__ char smem[];
    const uint32_t sb = smem_u32(smem);
    const int tid = threadIdx.x;
    const int wid = tid >> 5;
    const int lane = tid & 31;
    const int b = blockIdx.y;
    const int n0 = blockIdx.x * 128;

    const int WM = (wid & 3) * 32;      // warp m-offset (src rows)
    const int WN = (wid >> 2) * 32;     // warp n-offset (dst cols)

    const __half* gArow = gA + ((size_t)b * N_ + n0) * KS_;
    const __half* gBb   = gBt + (size_t)b * M_ * KS_;

    // ---- prologue: A resident (with SC0's group), SC0, SC1 ----
    #pragma unroll 4
    for (int i = 0; i < 16; ++i) {
        int idx = tid + i * THREADS;
        int c = idx >> 10, rem = idx & 1023, r = rem >> 3, q = rem & 7;
        cp_async16(sb + A_OFF + c * 16384 + SWZ(r * 128 + q * 16),
                   (const char*)(gArow + (size_t)r * KS_ + c * KC) + q * 16);
    }
    load_super(sb, gBb, 0, 0, 0, tid);
    cp_commit();                          // group: A + SC0
    load_super(sb, gBb, 0, 1, 1, tid);
    cp_commit();                          // group: SC1

    // per-thread ldmatrix lane addressing (non-trans, NT pattern)
    const int ra  = (lane & 7) + ((lane >> 3) & 1) * 8;   // A row within 16
    const int kba = (lane >> 4) * 16;                     // A k-half bytes
    const int nb  = (lane & 7) + ((lane >> 4) & 1) * 8;   // B n-row within 16
    const int kbb = ((lane >> 3) & 1) * 16;               // B k-half bytes

    float accm[2][4][4];   // x0*y0
    float accc[2][4][4];   // x1'*y0 + x0*y1'  (scale 2^-12)
    #pragma unroll
    for (int f = 0; f < 2; ++f)
        #pragma unroll
        for (int nf = 0; nf < 4; ++nf)
            #pragma unroll
            for (int k = 0; k < 4; ++k) { accm[f][nf][k] = 0.f; accc[f][nf][k] = 0.f; }

    float bestv[4] = {-1e30f, -1e30f, -1e30f, -1e30f};
    int   besti[4] = {0, 0, 0, 0};

    for (int SC = 0; SC < TSC; ++SC) {
        const int t = SC >> 2, kc = SC & 3, buf = SC % 3;
        if (SC == TSC - 1) cp_wait<0>(); else cp_wait<1>();
        __syncthreads();

        // prefetch SC+2 into buf (SC+2)%3 (held SC-1; barrier proved it free)
        if (SC + 2 < TSC) {
            const int S2 = SC + 2;
            load_super(sb, gBb, S2 >> 2, S2 & 3, S2 % 3, tid);
            cp_commit();
        }

        // ---- compute super-chunk: uniform 3-pair MMA block ----
        const uint32_t bb0 = sb + B_OFF + buf * 32768;
        const uint32_t bb1 = bb0 + 16384;
        const uint32_t ab0 = sb + A_OFF + kc * 16384;
        const uint32_t ab1 = sb + A_OFF + (4 + kc) * 16384;
        #pragma unroll
        for (int s = 0; s < 4; ++s) {
            uint32_t b0[2][4], b1[2][4];
            #pragma unroll
            for (int p = 0; p < 2; ++p) {
                ldm_x4(b0[p], bb0 + SWZ((WN + p * 16 + nb) * 128 + s * 32 + kbb));
                ldm_x4(b1[p], bb1 + SWZ((WN + p * 16 + nb) * 128 + s * 32 + kbb));
            }
            uint32_t a0[2][4], a1[2][4];
            #pragma unroll
            for (int f = 0; f < 2; ++f) {
                ldm_x4(a0[f], ab0 + SWZ((WM + f * 16 + ra) * 128 + s * 32 + kba));
                ldm_x4(a1[f], ab1 + SWZ((WM + f * 16 + ra) * 128 + s * 32 + kba));
            }
            #pragma unroll
            for (int f = 0; f < 2; ++f)
                #pragma unroll
                for (int nf = 0; nf < 4; ++nf) {
                    const uint32_t* bfr0 = &b0[nf >> 1][(nf & 1) * 2];
                    const uint32_t* bfr1 = &b1[nf >> 1][(nf & 1) * 2];
                    mma16816(accm[f][nf], a0[f], bfr0);
                    mma16816(accc[f][nf], a1[f], bfr0);
                    mma16816(accc[f][nf], a0[f], bfr1);
                }
        }

        // ---- tile epilogue: combine limbs, fold into argmax, reset ----
        if (kc == 3) {
            #pragma unroll
            for (int x = 0; x < 4; ++x) {
                const int f = x >> 1, hi = x & 1;
                float bv = bestv[x]; int bi = besti[x];
                #pragma unroll
                for (int nf = 0; nf < 4; ++nf) {
                    int nbase = t * 128 + WN + nf * 8 + (lane & 3) * 2;
                    float v0 = fmaf(accc[f][nf][hi * 2],     CROSS_SCALE, accm[f][nf][hi * 2]);
                    float v1 = fmaf(accc[f][nf][hi * 2 + 1], CROSS_SCALE, accm[f][nf][hi * 2 + 1]);
                    if (v0 > bv) { bv = v0; bi = nbase; }
                    if (v1 > bv) { bv = v1; bi = nbase + 1; }
                    accm[f][nf][hi * 2] = 0.f;     accc[f][nf][hi * 2] = 0.f;
                    accm[f][nf][hi * 2 + 1] = 0.f; accc[f][nf][hi * 2 + 1] = 0.f;
                }
                bestv[x] = bv; besti[x] = bi;
            }
        }
    }

    // ---- quad reduce: lanes sharing a row (lane^1, lane^2) ----
    #pragma unroll
    for (int x = 0; x < 4; ++x) {
        float v = bestv[x]; int i_ = besti[x];
        #pragma unroll
        for (int o = 1; o <= 2; o <<= 1) {
            float vo = __shfl_xor_sync(0xffffffffu, v, o);
            int   io = __shfl_xor_sync(0xffffffffu, i_, o);
            if (vo > v || (vo == v && io < i_)) { v = vo; i_ = io; }
        }
        bestv[x] = v; besti[x] = i_;
    }

    // ---- cross-warp-column combine via smem (reuse A region) ----
    float* sval = (float*)smem;          // [4][128]
    int*   sidx = (int*)(smem + 2048);   // [4][128]
    __syncthreads();
    if ((lane & 3) == 0) {
        const int col = wid >> 2;
        #pragma unroll
        for (int x = 0; x < 4; ++x) {
            int row = WM + (lane >> 2) + 8 * x;
            sval[col * 128 + row] = bestv[x];
            sidx[col * 128 + row] = besti[x];
        }
    }
    __syncthreads();
    if (tid < 128) {
        float bv = -1e30f;
        int   bi = 0x7fffffff;
        #pragma unroll
        for (int c = 0; c < 4; ++c) {
            float v = sval[c * 128 + tid];
            int  id = sidx[c * 128 + tid];
            if (v > bv || (v == bv && id < bi)) { bv = v; bi = id; }
        }
        int n = n0 + tid;
        size_t row = (size_t)b * N_ + n;
        out[row * 2 + 0] = pts[((size_t)b * M_ + bi) * 2 + 0];
        out[row * 2 + 1] = pts[((size_t)b * M_ + bi) * 2 + 1];
        out[(size_t)B_ * N_ * 2 + row] = bv;
    }
}

// ---------------------------------------------------------------------------
extern "C" void kernel_launch(void* const* d_in, const int* in_sizes, int n_in,
                              void* d_out, int out_size) {
    const float* desc_src   = (const float*)d_in[0];
    const float* desc_dst   = (const float*)d_in[1];
    const float* points_dst = (const float*)d_in[2];
    float* out = (float*)d_out;

    int total_rows = B_ * (N_ + M_);
    int nblocks = (total_rows + 7) / 8;
    prep_kernel<<<nblocks, 256>>>(desc_src, desc_dst);

    cudaFuncSetAttribute(match_mma_kernel,
                         cudaFuncAttributeMaxDynamicSharedMemorySize, SMEM_BYTES);
    dim3 grid(N_ / 128, B_);
    match_mma_kernel<<<grid, THREADS, SMEM_BYTES>>>(points_dst, out);
}